// round 6
// baseline (speedup 1.0000x reference)
#include <cuda_runtime.h>
#include <cuda_fp16.h>

#define B_ 8
#define N_ 1024
#define C_ 256
#define HD_ 256   // H*D
#define NEG_SLOPE 0.2f

struct alignas(8)  half4 { __half2 a, b; };
struct alignas(16) half8 { __half2 h0, h1, h2, h3; };

// Scratch (no cudaMalloc allowed)
__device__ __half g_Wxh[B_ * N_ * HD_];     // 16MB fp16 (aggregation gather)
__device__ float  g_ei [B_ * N_ * 4];
__device__ float  g_ej [B_ * N_ * 4];

// ---------------------------------------------------------------------------
// Kernel 1: Wx = x @ W  (M=8192, K=256, N=256), BM=128 BN=64 BK=32 TM=8 TN=4.
// Epilogue: writes fp16 Wx AND computes ei/ej directly (BN=64 == one head).
// No fp32 Wx is ever stored.
// ---------------------------------------------------------------------------
__global__ void __launch_bounds__(256)
gemm_kernel(const float* __restrict__ A,
            const float* __restrict__ Bm,
            const float* __restrict__ attn_a,
            __half* __restrict__ Ch,
            float* __restrict__ ei,
            float* __restrict__ ej) {
    __shared__ float As[128][33];   // [m][k], pad 1 -> conflict-free
    __shared__ float Bs[32][64];    // [k][n]

    const int tid = threadIdx.x;
    const int rowBase = blockIdx.x * 128;
    const int colBase = blockIdx.y * 64;
    const int h = blockIdx.y;               // head of this 64-col slice

    const int tx = tid & 15;        // 16 col groups * TN=4 -> 64
    const int ty = tid >> 4;        // 16 row groups * TM=8 -> 128

    const int ar0 = tid >> 3;
    const int af  = tid & 7;
    const int bkr = tid >> 3;

    float acc[8][4];
#pragma unroll
    for (int i = 0; i < 8; i++)
#pragma unroll
        for (int j = 0; j < 4; j++) acc[i][j] = 0.f;

    for (int kb = 0; kb < C_; kb += 32) {
#pragma unroll
        for (int i = 0; i < 4; i++) {
            int r = ar0 + 32 * i;
            float4 v = *(const float4*)(A + (size_t)(rowBase + r) * C_ + kb + af * 4);
            As[r][af * 4 + 0] = v.x;
            As[r][af * 4 + 1] = v.y;
            As[r][af * 4 + 2] = v.z;
            As[r][af * 4 + 3] = v.w;
        }
#pragma unroll
        for (int i = 0; i < 2; i++) {
            float4 v = *(const float4*)(Bm + (size_t)(kb + bkr) * HD_ + colBase + af * 8 + i * 4);
            *(float4*)(&Bs[bkr][af * 8 + i * 4]) = v;
        }
        __syncthreads();

#pragma unroll
        for (int k = 0; k < 32; k++) {
            float av[8];
#pragma unroll
            for (int i = 0; i < 8; i++) av[i] = As[ty * 8 + i][k];
            float4 bv = *(const float4*)(&Bs[k][tx * 4]);
#pragma unroll
            for (int i = 0; i < 8; i++) {
                acc[i][0] += av[i] * bv.x;
                acc[i][1] += av[i] * bv.y;
                acc[i][2] += av[i] * bv.z;
                acc[i][3] += av[i] * bv.w;
            }
        }
        __syncthreads();
    }

    // fp16 Wx store
#pragma unroll
    for (int i = 0; i < 8; i++) {
        size_t off = (size_t)(rowBase + ty * 8 + i) * HD_ + colBase + tx * 4;
        half4 hv;
        hv.a = __floats2half2_rn(acc[i][0], acc[i][1]);
        hv.b = __floats2half2_rn(acc[i][2], acc[i][3]);
        *(half4*)(Ch + off) = hv;
    }

    // eij epilogue: d-range of this thread = tx*4 .. tx*4+3 within head h
    float4 ai4 = *(const float4*)(attn_a + h * 128 + tx * 4);
    float4 aj4 = *(const float4*)(attn_a + h * 128 + 64 + tx * 4);
    const int lane = tid & 31;
#pragma unroll
    for (int i = 0; i < 8; i++) {
        float pi = acc[i][0] * ai4.x + acc[i][1] * ai4.y + acc[i][2] * ai4.z + acc[i][3] * ai4.w;
        float pj = acc[i][0] * aj4.x + acc[i][1] * aj4.y + acc[i][2] * aj4.z + acc[i][3] * aj4.w;
#pragma unroll
        for (int o = 8; o > 0; o >>= 1) {   // reduce across 16 tx lanes
            pi += __shfl_xor_sync(0xffffffffu, pi, o);
            pj += __shfl_xor_sync(0xffffffffu, pj, o);
        }
        if ((lane & 15) == 0) {
            int row = rowBase + ty * 8 + i;
            ei[row * 4 + h] = pi;
            ej[row * 4 + h] = pj;
        }
    }
}

// ---------------------------------------------------------------------------
// Kernel 2: warp-per-row GAT softmax + aggregation. 8 warps/CTA, no barriers.
// ---------------------------------------------------------------------------
__global__ void __launch_bounds__(256)
gat_kernel(const float* __restrict__ adj,
           const __half* __restrict__ Wxh,
           const float* __restrict__ ei,
           const float* __restrict__ ej,
           float* __restrict__ out) {
    __shared__ unsigned short s_idx[8][N_];
    __shared__ float s_e[8][128 * 4];       // exp chunk: 128 neighbors x 4 heads

    const int wid = threadIdx.x >> 5;
    const int lane = threadIdx.x & 31;
    const int row = blockIdx.x * 8 + wid;   // global (b*N+n)
    const int b = row >> 10;
    const int n = row & 1023;

    const float4* adj_row4 = (const float4*)(adj + (size_t)row * N_);

    // --- compaction: preload 32 adj values, ballot rounds (no barriers) ---
    float4 v[8];
#pragma unroll
    for (int r = 0; r < 8; r++) v[r] = adj_row4[r * 32 + lane];   // j = r*128+lane*4+c

    int base = 0;
    const unsigned lt = (1u << lane) - 1u;
#pragma unroll
    for (int r = 0; r < 8; r++) {
        float c0 = v[r].x, c1 = v[r].y, c2 = v[r].z, c3 = v[r].w;
        int j0 = r * 128 + lane * 4;
        unsigned m;
        bool p;
        p = (c0 != 0.f) || (j0 + 0 == n); m = __ballot_sync(0xffffffffu, p);
        if (p) s_idx[wid][base + __popc(m & lt)] = (unsigned short)(j0 + 0);
        base += __popc(m);
        p = (c1 != 0.f) || (j0 + 1 == n); m = __ballot_sync(0xffffffffu, p);
        if (p) s_idx[wid][base + __popc(m & lt)] = (unsigned short)(j0 + 1);
        base += __popc(m);
        p = (c2 != 0.f) || (j0 + 2 == n); m = __ballot_sync(0xffffffffu, p);
        if (p) s_idx[wid][base + __popc(m & lt)] = (unsigned short)(j0 + 2);
        base += __popc(m);
        p = (c3 != 0.f) || (j0 + 3 == n); m = __ballot_sync(0xffffffffu, p);
        if (p) s_idx[wid][base + __popc(m & lt)] = (unsigned short)(j0 + 3);
        base += __popc(m);
    }
    const int nnz = base;

    float4 ei4 = *(const float4*)(ei + (size_t)row * 4);
    const int h = lane >> 3;                 // head of this lane's 8 columns
    const __half* WxB = Wxh + (size_t)b * N_ * HD_ + lane * 8;

    float4 sum4 = make_float4(0.f, 0.f, 0.f, 0.f);
    float accA[4] = {0.f, 0.f, 0.f, 0.f};
    float accB[4] = {0.f, 0.f, 0.f, 0.f};

    for (int ck = 0; ck < nnz; ck += 128) {
        const int cn = min(128, nnz - ck);
        // phase A: compute exp(leaky(ei+ej)) into s_e (k-parallel over lanes)
        for (int kk = lane; kk < cn; kk += 32) {
            int j = s_idx[wid][ck + kk];
            float4 e4 = *(const float4*)(ej + ((size_t)(b * N_ + j)) * 4);
            e4.x += ei4.x; e4.y += ei4.y; e4.z += ei4.z; e4.w += ei4.w;
            e4.x = e4.x > 0.f ? e4.x : NEG_SLOPE * e4.x;
            e4.y = e4.y > 0.f ? e4.y : NEG_SLOPE * e4.y;
            e4.z = e4.z > 0.f ? e4.z : NEG_SLOPE * e4.z;
            e4.w = e4.w > 0.f ? e4.w : NEG_SLOPE * e4.w;
            e4.x = __expf(e4.x); e4.y = __expf(e4.y);
            e4.z = __expf(e4.z); e4.w = __expf(e4.w);
            sum4.x += e4.x; sum4.y += e4.y; sum4.z += e4.z; sum4.w += e4.w;
            ((float4*)s_e[wid])[kk] = e4;
        }
        __syncwarp();
        // phase B: every lane walks all k; one LDG.128 per k (coalesced/warp)
#pragma unroll 4
        for (int kk = 0; kk < cn; kk++) {
            int j = s_idx[wid][ck + kk];
            float c = s_e[wid][kk * 4 + h];
            half8 rv = *(const half8*)(WxB + (size_t)j * HD_);
            float2 f0 = __half22float2(rv.h0);
            float2 f1 = __half22float2(rv.h1);
            float2 f2 = __half22float2(rv.h2);
            float2 f3 = __half22float2(rv.h3);
            accA[0] += c * f0.x; accA[1] += c * f0.y;
            accA[2] += c * f1.x; accA[3] += c * f1.y;
            accB[0] += c * f2.x; accB[1] += c * f2.y;
            accB[2] += c * f3.x; accB[3] += c * f3.y;
        }
        __syncwarp();
    }

    // reduce sum4 across warp (every lane ends with the full per-head sums)
#pragma unroll
    for (int o = 16; o > 0; o >>= 1) {
        sum4.x += __shfl_xor_sync(0xffffffffu, sum4.x, o);
        sum4.y += __shfl_xor_sync(0xffffffffu, sum4.y, o);
        sum4.z += __shfl_xor_sync(0xffffffffu, sum4.z, o);
        sum4.w += __shfl_xor_sync(0xffffffffu, sum4.w, o);
    }
    float sum_h = (h == 0) ? sum4.x : (h == 1) ? sum4.y : (h == 2) ? sum4.z : sum4.w;
    float rs = 1.f / sum_h;

    float* o0 = out + (size_t)row * HD_ + lane * 8;
    *(float4*)(o0)     = make_float4(accA[0] * rs, accA[1] * rs, accA[2] * rs, accA[3] * rs);
    *(float4*)(o0 + 4) = make_float4(accB[0] * rs, accB[1] * rs, accB[2] * rs, accB[3] * rs);
}

// ---------------------------------------------------------------------------
extern "C" void kernel_launch(void* const* d_in, const int* in_sizes, int n_in,
                              void* d_out, int out_size) {
    const float* x   = (const float*)d_in[0];   // (8,1024,256)
    const float* adj = (const float*)d_in[1];   // (8,1024,1024)
    const float* W   = (const float*)d_in[2];   // (256,256)
    const float* a   = (const float*)d_in[3];   // (1,4,128)
    float* out = (float*)d_out;

    __half* Wxh; cudaGetSymbolAddress((void**)&Wxh, g_Wxh);
    float*  ei;  cudaGetSymbolAddress((void**)&ei,  g_ei);
    float*  ej;  cudaGetSymbolAddress((void**)&ej,  g_ej);

    dim3 ggrid(B_ * N_ / 128, HD_ / 64);
    gemm_kernel<<<ggrid, 256>>>(x, W, a, Wxh, ei, ej);
    gat_kernel<<<B_ * N_ / 8, 256>>>(adj, Wxh, ei, ej, out);
}